// round 15
// baseline (speedup 1.0000x reference)
#include <cuda_runtime.h>
#include <cuda_fp16.h>
#include <cstdint>

// Problem constants
#define E_    16384
#define D_    1024
#define A_    512
#define M_    2048
#define H_    3
#define NRES_ 3

// ---------------------------------------------------------------------------
// Scratch (device globals — no runtime allocation allowed)
// ---------------------------------------------------------------------------
__device__ __half g_Qh [E_ * D_];            // normalized h[src], fp16
__device__ __half g_Kh [E_ * D_];            // rep[dst], fp16
__device__ float  g_Qp [H_ * E_ * A_];       // Q proj fp32, later attn_out fp32
__device__ float  g_Kp [H_ * E_ * A_];       // K proj fp32
__device__ float  g_Vp [H_ * E_ * A_];       // V proj fp32
__device__ __half g_AOh[H_ * E_ * A_];       // attn_out fp16
__device__ float  g_m  [H_ * E_ * M_];       // MLP state fp32
__device__ __half g_xnh[H_ * E_ * M_];       // layernormed state fp16
__device__ __half g_mh [H_ * E_ * M_];       // final m fp16
__device__ __half g_HOh[H_ * E_ * A_];       // head_out fp16
// transposed fp16 weights  (Bt layout: [N, K])
__device__ __half g_Wqt [H_ * A_ * D_];
__device__ __half g_Wkt [H_ * A_ * D_];
__device__ __half g_Wvt [H_ * A_ * D_];
__device__ __half g_W0t [H_ * M_ * A_];
__device__ __half g_Wrt [H_ * NRES_ * M_ * M_];
__device__ __half g_Wmst[H_ * A_ * M_];
__device__ __half g_Wuast[H_ * D_ * A_];

// ---------------------------------------------------------------------------
// helpers
// ---------------------------------------------------------------------------
__device__ __forceinline__ uint32_t s2u(const void* p) {
    uint32_t a;
    asm("{ .reg .u64 t; cvta.to.shared.u64 t, %1; cvt.u32.u64 %0, t; }"
        : "=r"(a) : "l"(p));
    return a;
}
__device__ __forceinline__ void cp16(uint32_t dst, const void* src) {
    asm volatile("cp.async.cg.shared.global [%0], [%1], 16;"
                 :: "r"(dst), "l"(src) : "memory");
}
__device__ __forceinline__ void ldsm4(uint32_t* r, uint32_t addr) {
    asm volatile("ldmatrix.sync.aligned.m8n8.x4.shared.b16 {%0,%1,%2,%3}, [%4];"
                 : "=r"(r[0]), "=r"(r[1]), "=r"(r[2]), "=r"(r[3]) : "r"(addr));
}

// ---------------------------------------------------------------------------
// Kernel 1: gather + L2-normalize Q, gather K, seed out = Q - K, fp16 copies
// ---------------------------------------------------------------------------
__global__ __launch_bounds__(256) void gather_k(
    const float* __restrict__ h, const float* __restrict__ rep,
    const int* __restrict__ src, const int* __restrict__ dst,
    float* __restrict__ out)
{
    const int e = blockIdx.x;
    const int t = threadIdx.x;
    const float4 hv = ((const float4*)(h   + (size_t)src[e] * D_))[t];
    const float4 kv = ((const float4*)(rep + (size_t)dst[e] * D_))[t];

    float ss = hv.x*hv.x + hv.y*hv.y + hv.z*hv.z + hv.w*hv.w;
    #pragma unroll
    for (int o = 16; o; o >>= 1) ss += __shfl_xor_sync(0xffffffffu, ss, o);
    __shared__ float red[8];
    if ((t & 31) == 0) red[t >> 5] = ss;
    __syncthreads();
    float tot = 0.f;
    #pragma unroll
    for (int i = 0; i < 8; i++) tot += red[i];

    const float inv = 1.f / fmaxf(sqrtf(tot), 1e-12f);
    const float4 q = make_float4(hv.x*inv, hv.y*inv, hv.z*inv, hv.w*inv);

    const size_t base = (size_t)e * D_;
    ((float4*)(out + base))[t] = make_float4(q.x-kv.x, q.y-kv.y, q.z-kv.z, q.w-kv.w);
    __half2* qh = (__half2*)(g_Qh + base);
    __half2* kh = (__half2*)(g_Kh + base);
    qh[t*2+0] = __floats2half2_rn(q.x,  q.y);
    qh[t*2+1] = __floats2half2_rn(q.z,  q.w);
    kh[t*2+0] = __floats2half2_rn(kv.x, kv.y);
    kh[t*2+1] = __floats2half2_rn(kv.z, kv.w);
}

// ---------------------------------------------------------------------------
// Kernel 2: transpose + fp32 -> fp16 weight convert.  in [R,C] -> out [C,R]
// ---------------------------------------------------------------------------
__global__ __launch_bounds__(256) void tconv_k(
    const float* __restrict__ in, __half* __restrict__ out, int R, int C)
{
    __shared__ float tile[32][33];
    const int t  = threadIdx.x;
    const int tx = t & 31, ty = t >> 5;
    const int bx = blockIdx.x * 32;
    const int by = blockIdx.y * 32;
    #pragma unroll
    for (int i = 0; i < 4; i++)
        tile[ty + i*8][tx] = in[(size_t)(by + ty + i*8) * C + bx + tx];
    __syncthreads();
    #pragma unroll
    for (int i = 0; i < 4; i++)
        out[(size_t)(bx + ty + i*8) * R + by + tx] = __float2half_rn(tile[tx][ty + i*8]);
}

// ---------------------------------------------------------------------------
// Kernel 3: fp16 mma.sync GEMM.  C = epi( A[M,K] @ Bt[N,K]^T )
//   CTA tile 128x128, BK=32, 8 warps (4m x 2n), warp tile 32x64,
//   m16n8k16 atoms 2x8, ldmatrix frags, cp.async double buffer.
//   mode bit0: +bias[j]  bit1: relu  bit3: +Res  bit2: +Cin
//   bit4: fp16 copy to Ohf          bit5: suppress fp32 write
// ---------------------------------------------------------------------------
#define BMT 128
#define BNT 128
#define BKT 32
#define ROWB 80                 // bytes per smem row: 32 fp16 + 8 pad
#define TILEB (128 * ROWB)      // 10240 bytes per operand tile

__global__ __launch_bounds__(256, 2) void tgemm_k(
    const __half* __restrict__ A,
    const __half* __restrict__ Bt,
    const float* __restrict__ bias,
    const float* __restrict__ Cin,
    const float* __restrict__ Res,
    float* __restrict__ Cout,
    __half* __restrict__ Ohf,
    int Nd, int Kd, int mode)
{
    __shared__ __align__(16) char sm[4 * TILEB];   // [stage][A|B]
    const uint32_t smb = s2u(sm);

    const int t   = threadIdx.x;
    const int w   = t >> 5, lid = t & 31;
    const int wm  = w & 3,  wn  = w >> 2;
    const int bm  = blockIdx.y * BMT;
    const int bn  = blockIdx.x * BNT;

    float acc[2][8][4];
    #pragma unroll
    for (int i = 0; i < 2; i++)
        #pragma unroll
        for (int j = 0; j < 8; j++)
            #pragma unroll
            for (int k = 0; k < 4; k++) acc[i][j][k] = 0.f;

    const int ldRow = t >> 2, ldSeg = t & 3;       // 64 rows x 4 segs per 256-thr pass

    auto issue = [&](int kc, int s) {
        const uint32_t sa = smb + s * 2 * TILEB;
        const uint32_t sb = sa + TILEB;
        const int k0 = kc * BKT;
        #pragma unroll
        for (int i = 0; i < 2; i++) {
            const int row = ldRow + i * 64;
            const uint32_t soff = (uint32_t)row * ROWB + ldSeg * 16;
            cp16(sa + soff, A  + (size_t)(bm + row) * Kd + k0 + ldSeg * 8);
            cp16(sb + soff, Bt + (size_t)(bn + row) * Kd + k0 + ldSeg * 8);
        }
        asm volatile("cp.async.commit_group;" ::: "memory");
    };

    const int nch = Kd / BKT;
    issue(0, 0);

    // precomputed lane pieces for ldmatrix addressing
    const uint32_t aRowOff = (uint32_t)(wm * 32 + (lid & 15)) * ROWB + (lid >> 4) * 16;
    const uint32_t bRowOff = (uint32_t)(wn * 64 + (lid & 7) + ((lid >> 4) & 1) * 8) * ROWB
                           + ((lid >> 3) & 1) * 16;

    for (int kc = 0; kc < nch; kc++) {
        if (kc + 1 < nch) {
            issue(kc + 1, (kc + 1) & 1);
            asm volatile("cp.async.wait_group 1;" ::: "memory");
        } else {
            asm volatile("cp.async.wait_group 0;" ::: "memory");
        }
        __syncthreads();

        const uint32_t sa = smb + (kc & 1) * 2 * TILEB;
        const uint32_t sb = sa + TILEB;

        #pragma unroll
        for (int kk = 0; kk < 2; kk++) {           // two k16 steps in BK=32
            uint32_t af[2][4], bf[4][4];
            #pragma unroll
            for (int am = 0; am < 2; am++)
                ldsm4(af[am], sa + aRowOff + (uint32_t)am * 16 * ROWB + kk * 32);
            #pragma unroll
            for (int p = 0; p < 4; p++)
                ldsm4(bf[p], sb + bRowOff + (uint32_t)p * 16 * ROWB + kk * 32);

            #pragma unroll
            for (int am = 0; am < 2; am++)
                #pragma unroll
                for (int p = 0; p < 4; p++) {
                    asm volatile(
                        "mma.sync.aligned.m16n8k16.row.col.f32.f16.f16.f32 "
                        "{%0,%1,%2,%3}, {%4,%5,%6,%7}, {%8,%9}, {%0,%1,%2,%3};"
                        : "+f"(acc[am][2*p][0]), "+f"(acc[am][2*p][1]),
                          "+f"(acc[am][2*p][2]), "+f"(acc[am][2*p][3])
                        : "r"(af[am][0]), "r"(af[am][1]), "r"(af[am][2]), "r"(af[am][3]),
                          "r"(bf[p][0]), "r"(bf[p][1]));
                    asm volatile(
                        "mma.sync.aligned.m16n8k16.row.col.f32.f16.f16.f32 "
                        "{%0,%1,%2,%3}, {%4,%5,%6,%7}, {%8,%9}, {%0,%1,%2,%3};"
                        : "+f"(acc[am][2*p+1][0]), "+f"(acc[am][2*p+1][1]),
                          "+f"(acc[am][2*p+1][2]), "+f"(acc[am][2*p+1][3])
                        : "r"(af[am][0]), "r"(af[am][1]), "r"(af[am][2]), "r"(af[am][3]),
                          "r"(bf[p][2]), "r"(bf[p][3]));
                }
        }
        __syncthreads();
    }

    // ---------------- epilogue ----------------
    const int lrow = lid >> 2;
    const int lcol = (lid & 3) * 2;
    #pragma unroll
    for (int am = 0; am < 2; am++) {
        #pragma unroll
        for (int rr = 0; rr < 2; rr++) {
            const int grow = bm + wm * 32 + am * 16 + rr * 8 + lrow;
            const size_t rbase = (size_t)grow * Nd;
            #pragma unroll
            for (int an = 0; an < 8; an++) {
                const int gcol = bn + wn * 64 + an * 8 + lcol;
                float v0 = acc[am][an][rr * 2 + 0];
                float v1 = acc[am][an][rr * 2 + 1];
                if (mode & 1) {
                    const float2 bv = *(const float2*)&bias[gcol];
                    v0 += bv.x; v1 += bv.y;
                }
                if (mode & 2) { v0 = fmaxf(v0, 0.f); v1 = fmaxf(v1, 0.f); }
                if (mode & 8) {
                    const float2 rv = *(const float2*)&Res[rbase + gcol];
                    v0 += rv.x; v1 += rv.y;
                }
                if (mode & 4) {
                    const float2 cv = *(const float2*)&Cin[rbase + gcol];
                    v0 += cv.x; v1 += cv.y;
                }
                if (!(mode & 32))
                    *(float2*)&Cout[rbase + gcol] = make_float2(v0, v1);
                if (mode & 16)
                    *(__half2*)&Ohf[rbase + gcol] = __floats2half2_rn(v0, v1);
            }
        }
    }
}

// ---------------------------------------------------------------------------
// Kernel 4: feature-dim softmax attention (fp32 in, fp32 + fp16 out)
// ---------------------------------------------------------------------------
__global__ __launch_bounds__(128) void attn_k(
    const float* Qp, const float* __restrict__ Kp,
    const float* __restrict__ Vp, float* AO, __half* AOh)
{
    const int r = blockIdx.x;
    const int t = threadIdx.x;
    const size_t base = (size_t)r * A_;

    const float4 qp = ((const float4*)(Qp + base))[t];
    const float4 kp = ((const float4*)(Kp + base))[t];
    const float4 vp = ((const float4*)(Vp + base))[t];

    const float sc = 0.04419417382415922f;   // 1/sqrt(512)
    const float s0 = qp.x*kp.x*sc, s1 = qp.y*kp.y*sc;
    const float s2 = qp.z*kp.z*sc, s3 = qp.w*kp.w*sc;

    float mx = fmaxf(fmaxf(s0,s1), fmaxf(s2,s3));
    #pragma unroll
    for (int o = 16; o; o >>= 1) mx = fmaxf(mx, __shfl_xor_sync(0xffffffffu, mx, o));
    __shared__ float rmx[4];
    if ((t & 31) == 0) rmx[t >> 5] = mx;
    __syncthreads();
    mx = fmaxf(fmaxf(rmx[0], rmx[1]), fmaxf(rmx[2], rmx[3]));

    const float e0 = expf(s0-mx), e1 = expf(s1-mx);
    const float e2 = expf(s2-mx), e3 = expf(s3-mx);
    float smv = e0 + e1 + e2 + e3;
    #pragma unroll
    for (int o = 16; o; o >>= 1) smv += __shfl_xor_sync(0xffffffffu, smv, o);
    __shared__ float rsm[4];
    if ((t & 31) == 0) rsm[t >> 5] = smv;
    __syncthreads();
    smv = rsm[0] + rsm[1] + rsm[2] + rsm[3];

    const float inv = 1.f / smv;
    const float a0 = e0*inv*vp.x, a1 = e1*inv*vp.y;
    const float a2 = e2*inv*vp.z, a3 = e3*inv*vp.w;
    ((float4*)(AO + base))[t] = make_float4(a0, a1, a2, a3);
    __half2* oh = (__half2*)(AOh + base);
    oh[t*2+0] = __floats2half2_rn(a0, a1);
    oh[t*2+1] = __floats2half2_rn(a2, a3);
}

// ---------------------------------------------------------------------------
// Kernel 5: layernorm over M=2048, fp32 in -> fp16 out
// ---------------------------------------------------------------------------
__global__ __launch_bounds__(256) void ln_k(
    const float* __restrict__ X, __half* __restrict__ Y,
    const float* __restrict__ gln, const float* __restrict__ bln, int j)
{
    const int r  = blockIdx.x;
    const int t  = threadIdx.x;
    const int hh = r >> 14;                       // r / E_
    const size_t base = (size_t)r * M_;

    const float4* x4 = (const float4*)(X + base);
    const float4 x0 = x4[t];
    const float4 x1 = x4[t + 256];

    float s  = x0.x+x0.y+x0.z+x0.w + x1.x+x1.y+x1.z+x1.w;
    float sq = x0.x*x0.x+x0.y*x0.y+x0.z*x0.z+x0.w*x0.w
             + x1.x*x1.x+x1.y*x1.y+x1.z*x1.z+x1.w*x1.w;
    #pragma unroll
    for (int o = 16; o; o >>= 1) {
        s  += __shfl_xor_sync(0xffffffffu, s,  o);
        sq += __shfl_xor_sync(0xffffffffu, sq, o);
    }
    __shared__ float rs[8], rq[8];
    if ((t & 31) == 0) { rs[t>>5] = s; rq[t>>5] = sq; }
    __syncthreads();
    float st = 0.f, qt = 0.f;
    #pragma unroll
    for (int i = 0; i < 8; i++) { st += rs[i]; qt += rq[i]; }

    const float mu   = st * (1.f / M_);
    const float var  = fmaxf(qt * (1.f / M_) - mu*mu, 0.f);
    const float rstd = rsqrtf(var + 1e-5f);

    const size_t goff = (size_t)(hh * NRES_ + j) * M_;
    const float4* g4 = (const float4*)(gln + goff);
    const float4* b4 = (const float4*)(bln + goff);
    const float4 g0 = g4[t], g1 = g4[t+256];
    const float4 b0 = b4[t], b1 = b4[t+256];

    __half2* y2 = (__half2*)(Y + base);
    y2[t*2+0] = __floats2half2_rn((x0.x-mu)*rstd*g0.x + b0.x, (x0.y-mu)*rstd*g0.y + b0.y);
    y2[t*2+1] = __floats2half2_rn((x0.z-mu)*rstd*g0.z + b0.z, (x0.w-mu)*rstd*g0.w + b0.w);
    y2[(t+256)*2+0] = __floats2half2_rn((x1.x-mu)*rstd*g1.x + b1.x, (x1.y-mu)*rstd*g1.y + b1.y);
    y2[(t+256)*2+1] = __floats2half2_rn((x1.z-mu)*rstd*g1.z + b1.z, (x1.w-mu)*rstd*g1.w + b1.w);
}

// ---------------------------------------------------------------------------
// Orchestration
// ---------------------------------------------------------------------------
extern "C" void kernel_launch(void* const* d_in, const int* in_sizes, int n_in,
                              void* d_out, int out_size)
{
    const float* h    = (const float*)d_in[0];
    const float* rep  = (const float*)d_in[1];
    const int*   src  = (const int*)  d_in[2];
    const int*   dst  = (const int*)  d_in[3];
    const float* Wq   = (const float*)d_in[4];
    const float* bq   = (const float*)d_in[5];
    const float* Wk   = (const float*)d_in[6];
    const float* bk   = (const float*)d_in[7];
    const float* Wv   = (const float*)d_in[8];
    const float* bv   = (const float*)d_in[9];
    const float* W0   = (const float*)d_in[10];
    const float* b0   = (const float*)d_in[11];
    const float* Wr   = (const float*)d_in[12];
    const float* br   = (const float*)d_in[13];
    const float* gln  = (const float*)d_in[14];
    const float* bln  = (const float*)d_in[15];
    const float* Wms  = (const float*)d_in[16];
    const float* bms  = (const float*)d_in[17];
    const float* Wuas = (const float*)d_in[18];
    float* out = (float*)d_out;

    __half *Qh, *Kh, *AOh, *xnh, *mh, *HOh;
    __half *Wqt, *Wkt, *Wvt, *W0t, *Wrt, *Wmst, *Wuast;
    float *Qp, *Kp, *Vp, *mB;
    cudaGetSymbolAddress((void**)&Qh,   g_Qh);
    cudaGetSymbolAddress((void**)&Kh,   g_Kh);
    cudaGetSymbolAddress((void**)&Qp,   g_Qp);
    cudaGetSymbolAddress((void**)&Kp,   g_Kp);
    cudaGetSymbolAddress((void**)&Vp,   g_Vp);
    cudaGetSymbolAddress((void**)&AOh,  g_AOh);
    cudaGetSymbolAddress((void**)&mB,   g_m);
    cudaGetSymbolAddress((void**)&xnh,  g_xnh);
    cudaGetSymbolAddress((void**)&mh,   g_mh);
    cudaGetSymbolAddress((void**)&HOh,  g_HOh);
    cudaGetSymbolAddress((void**)&Wqt,  g_Wqt);
    cudaGetSymbolAddress((void**)&Wkt,  g_Wkt);
    cudaGetSymbolAddress((void**)&Wvt,  g_Wvt);
    cudaGetSymbolAddress((void**)&W0t,  g_W0t);
    cudaGetSymbolAddress((void**)&Wrt,  g_Wrt);
    cudaGetSymbolAddress((void**)&Wmst, g_Wmst);
    cudaGetSymbolAddress((void**)&Wuast,g_Wuast);

    auto tconv = [](const float* in, __half* o, int R, int C) {
        dim3 g(C / 32, R / 32);
        tconv_k<<<g, 256>>>(in, o, R, C);
    };
    auto gemm = [](const __half* Aa, const __half* Bt,
                   const float* bias, const float* Cin, const float* Res,
                   float* Co, __half* Oh, int Md, int Nd, int Kd, int mode) {
        dim3 grid(Nd / BNT, Md / BMT);
        tgemm_k<<<grid, 256>>>(Aa, Bt, bias, Cin, Res, Co, Oh, Nd, Kd, mode);
    };

    // 0. weight transpose + convert  (in [K,N] fp32 -> out [N,K] fp16)
    for (int hh = 0; hh < H_; hh++) {
        tconv(Wq + (size_t)hh*D_*A_, Wqt + (size_t)hh*A_*D_, D_, A_);
        tconv(Wk + (size_t)hh*D_*A_, Wkt + (size_t)hh*A_*D_, D_, A_);
        tconv(Wv + (size_t)hh*D_*A_, Wvt + (size_t)hh*A_*D_, D_, A_);
        tconv(W0 + (size_t)hh*A_*M_, W0t + (size_t)hh*M_*A_, A_, M_);
        for (int j = 0; j < NRES_; j++)
            tconv(Wr  + (size_t)(hh*NRES_+j)*M_*M_, Wrt + (size_t)(hh*NRES_+j)*M_*M_, M_, M_);
        tconv(Wms  + (size_t)hh*M_*A_, Wmst  + (size_t)hh*A_*M_, M_, A_);
        tconv(Wuas + (size_t)hh*A_*D_, Wuast + (size_t)hh*D_*A_, A_, D_);
    }

    // 1. gather + normalize + seed out = Q - K  (+ fp16 Q,K)
    gather_k<<<E_, 256>>>(h, rep, src, dst, out);

    // 2. per-head QKV projections
    for (int hh = 0; hh < H_; hh++) {
        const size_t wOff = (size_t)hh * A_ * D_;
        const size_t oOff = (size_t)hh * E_ * A_;
        gemm(Qh, Wqt + wOff, bq + hh*A_, nullptr, nullptr, Qp + oOff, nullptr, E_, A_, D_, 1);
        gemm(Kh, Wkt + wOff, bk + hh*A_, nullptr, nullptr, Kp + oOff, nullptr, E_, A_, D_, 1);
        gemm(Kh, Wvt + wOff, bv + hh*A_, nullptr, nullptr, Vp + oOff, nullptr, E_, A_, D_, 1);
    }

    // 3. feature-dim softmax attention; attn_out -> Qp (fp32) + AOh (fp16)
    attn_k<<<H_ * E_, 128>>>(Qp, Kp, Vp, Qp, AOh);

    // 4. m = attn_out @ W0 + b0
    for (int hh = 0; hh < H_; hh++)
        gemm(AOh + (size_t)hh*E_*A_, W0t + (size_t)hh*M_*A_, b0 + hh*M_,
             nullptr, nullptr, mB + (size_t)hh*E_*M_, nullptr, E_, M_, A_, 1);

    // 5. ResNet blocks: xn = LN(m); m += relu(xn @ Wr + br)
    for (int j = 0; j < NRES_; j++) {
        ln_k<<<H_ * E_, 256>>>(mB, xnh, gln, bln, j);
        const int mode = (j == NRES_ - 1) ? (1|2|4|16) : (1|2|4);
        for (int hh = 0; hh < H_; hh++) {
            const size_t mOff = (size_t)hh * E_ * M_;
            const size_t wOff = (size_t)(hh * NRES_ + j) * M_ * M_;
            gemm(xnh + mOff, Wrt + wOff, br + (hh*NRES_ + j)*M_,
                 mB + mOff, nullptr, mB + mOff, mh + mOff, E_, M_, M_, mode);
        }
    }

    // 6. head_out = m @ Wms + bms + attn_out  (fp16 only)
    for (int hh = 0; hh < H_; hh++)
        gemm(mh + (size_t)hh*E_*M_, Wmst + (size_t)hh*A_*M_, bms + hh*A_,
             nullptr, Qp + (size_t)hh*E_*A_, nullptr, HOh + (size_t)hh*E_*A_,
             E_, A_, M_, 1|8|16|32);

    // 7. out += head_out[h] @ Wuas[h]   (out already holds Q-K)
    for (int hh = 0; hh < H_; hh++)
        gemm(HOh + (size_t)hh*E_*A_, Wuast + (size_t)hh*D_*A_, nullptr,
             out, nullptr, out, nullptr, E_, D_, A_, 4);
}

// round 16
// speedup vs baseline: 1.0007x; 1.0007x over previous
#include <cuda_runtime.h>
#include <cuda_fp16.h>
#include <cstdint>

// Problem constants
#define E_    16384
#define D_    1024
#define A_    512
#define M_    2048
#define H_    3
#define NRES_ 3

// ---------------------------------------------------------------------------
// Scratch (device globals — no runtime allocation allowed)
// ---------------------------------------------------------------------------
__device__ __half g_Qh [E_ * D_];            // normalized h[src], fp16
__device__ __half g_Kh [E_ * D_];            // rep[dst], fp16
__device__ float  g_Qp [H_ * E_ * A_];       // Q proj fp32, later attn_out fp32
__device__ float  g_Kp [H_ * E_ * A_];       // K proj fp32
__device__ float  g_Vp [H_ * E_ * A_];       // V proj fp32
__device__ __half g_AOh[H_ * E_ * A_];       // attn_out fp16
__device__ float  g_m  [H_ * E_ * M_];       // MLP state fp32
__device__ __half g_xnh[H_ * E_ * M_];       // layernormed state fp16
__device__ __half g_mh [H_ * E_ * M_];       // final m fp16
__device__ __half g_HOh[H_ * E_ * A_];       // head_out fp16
// transposed fp16 weights  (Bt layout: [N, K])
__device__ __half g_Wqt [H_ * A_ * D_];
__device__ __half g_Wkt [H_ * A_ * D_];
__device__ __half g_Wvt [H_ * A_ * D_];
__device__ __half g_W0t [H_ * M_ * A_];
__device__ __half g_Wrt [H_ * NRES_ * M_ * M_];
__device__ __half g_Wmst[H_ * A_ * M_];
__device__ __half g_Wuast[H_ * D_ * A_];

// ---------------------------------------------------------------------------
// helpers
// ---------------------------------------------------------------------------
__device__ __forceinline__ uint32_t s2u(const void* p) {
    uint32_t a;
    asm("{ .reg .u64 t; cvta.to.shared.u64 t, %1; cvt.u32.u64 %0, t; }"
        : "=r"(a) : "l"(p));
    return a;
}
__device__ __forceinline__ void cp16(uint32_t dst, const void* src) {
    asm volatile("cp.async.cg.shared.global [%0], [%1], 16;"
                 :: "r"(dst), "l"(src) : "memory");
}
__device__ __forceinline__ void ldsm4(uint32_t* r, uint32_t addr) {
    asm volatile("ldmatrix.sync.aligned.m8n8.x4.shared.b16 {%0,%1,%2,%3}, [%4];"
                 : "=r"(r[0]), "=r"(r[1]), "=r"(r[2]), "=r"(r[3]) : "r"(addr));
}

// ---------------------------------------------------------------------------
// Kernel 1: gather + L2-normalize Q, gather K, seed out = Q - K, fp16 copies
// ---------------------------------------------------------------------------
__global__ __launch_bounds__(256) void gather_k(
    const float* __restrict__ h, const float* __restrict__ rep,
    const int* __restrict__ src, const int* __restrict__ dst,
    float* __restrict__ out)
{
    const int e = blockIdx.x;
    const int t = threadIdx.x;
    const float4 hv = ((const float4*)(h   + (size_t)src[e] * D_))[t];
    const float4 kv = ((const float4*)(rep + (size_t)dst[e] * D_))[t];

    float ss = hv.x*hv.x + hv.y*hv.y + hv.z*hv.z + hv.w*hv.w;
    #pragma unroll
    for (int o = 16; o; o >>= 1) ss += __shfl_xor_sync(0xffffffffu, ss, o);
    __shared__ float red[8];
    if ((t & 31) == 0) red[t >> 5] = ss;
    __syncthreads();
    float tot = 0.f;
    #pragma unroll
    for (int i = 0; i < 8; i++) tot += red[i];

    const float inv = 1.f / fmaxf(sqrtf(tot), 1e-12f);
    const float4 q = make_float4(hv.x*inv, hv.y*inv, hv.z*inv, hv.w*inv);

    const size_t base = (size_t)e * D_;
    ((float4*)(out + base))[t] = make_float4(q.x-kv.x, q.y-kv.y, q.z-kv.z, q.w-kv.w);
    __half2* qh = (__half2*)(g_Qh + base);
    __half2* kh = (__half2*)(g_Kh + base);
    qh[t*2+0] = __floats2half2_rn(q.x,  q.y);
    qh[t*2+1] = __floats2half2_rn(q.z,  q.w);
    kh[t*2+0] = __floats2half2_rn(kv.x, kv.y);
    kh[t*2+1] = __floats2half2_rn(kv.z, kv.w);
}

// ---------------------------------------------------------------------------
// Kernel 2: transpose + fp32 -> fp16 weight convert.  in [R,C] -> out [C,R]
// ---------------------------------------------------------------------------
__global__ __launch_bounds__(256) void tconv_k(
    const float* __restrict__ in, __half* __restrict__ out, int R, int C)
{
    __shared__ float tile[32][33];
    const int t  = threadIdx.x;
    const int tx = t & 31, ty = t >> 5;
    const int bx = blockIdx.x * 32;
    const int by = blockIdx.y * 32;
    #pragma unroll
    for (int i = 0; i < 4; i++)
        tile[ty + i*8][tx] = in[(size_t)(by + ty + i*8) * C + bx + tx];
    __syncthreads();
    #pragma unroll
    for (int i = 0; i < 4; i++)
        out[(size_t)(bx + ty + i*8) * R + by + tx] = __float2half_rn(tile[tx][ty + i*8]);
}

// ---------------------------------------------------------------------------
// Kernel 3: fp16 mma.sync GEMM.  C = epi( A[M,K] @ Bt[N,K]^T )
//   CTA tile 128x128, BK=32, 8 warps (4m x 2n), warp tile 32x64,
//   m16n8k16 atoms 2x8, ldmatrix frags, cp.async double buffer.
//   mode bit0: +bias[j]  bit1: relu  bit3: +Res  bit2: +Cin
//   bit4: fp16 copy to Ohf          bit5: suppress fp32 write
// ---------------------------------------------------------------------------
#define BMT 128
#define BNT 128
#define BKT 32
#define ROWB 80                 // bytes per smem row: 32 fp16 + 8 pad
#define TILEB (128 * ROWB)      // 10240 bytes per operand tile

__global__ __launch_bounds__(256, 2) void tgemm_k(
    const __half* __restrict__ A,
    const __half* __restrict__ Bt,
    const float* __restrict__ bias,
    const float* __restrict__ Cin,
    const float* __restrict__ Res,
    float* __restrict__ Cout,
    __half* __restrict__ Ohf,
    int Nd, int Kd, int mode)
{
    __shared__ __align__(16) char sm[4 * TILEB];   // [stage][A|B]
    const uint32_t smb = s2u(sm);

    const int t   = threadIdx.x;
    const int w   = t >> 5, lid = t & 31;
    const int wm  = w & 3,  wn  = w >> 2;
    const int bm  = blockIdx.y * BMT;
    const int bn  = blockIdx.x * BNT;

    float acc[2][8][4];
    #pragma unroll
    for (int i = 0; i < 2; i++)
        #pragma unroll
        for (int j = 0; j < 8; j++)
            #pragma unroll
            for (int k = 0; k < 4; k++) acc[i][j][k] = 0.f;

    const int ldRow = t >> 2, ldSeg = t & 3;       // 64 rows x 4 segs per 256-thr pass

    auto issue = [&](int kc, int s) {
        const uint32_t sa = smb + s * 2 * TILEB;
        const uint32_t sb = sa + TILEB;
        const int k0 = kc * BKT;
        #pragma unroll
        for (int i = 0; i < 2; i++) {
            const int row = ldRow + i * 64;
            const uint32_t soff = (uint32_t)row * ROWB + ldSeg * 16;
            cp16(sa + soff, A  + (size_t)(bm + row) * Kd + k0 + ldSeg * 8);
            cp16(sb + soff, Bt + (size_t)(bn + row) * Kd + k0 + ldSeg * 8);
        }
        asm volatile("cp.async.commit_group;" ::: "memory");
    };

    const int nch = Kd / BKT;
    issue(0, 0);

    // precomputed lane pieces for ldmatrix addressing
    const uint32_t aRowOff = (uint32_t)(wm * 32 + (lid & 15)) * ROWB + (lid >> 4) * 16;
    const uint32_t bRowOff = (uint32_t)(wn * 64 + (lid & 7) + ((lid >> 4) & 1) * 8) * ROWB
                           + ((lid >> 3) & 1) * 16;

    for (int kc = 0; kc < nch; kc++) {
        if (kc + 1 < nch) {
            issue(kc + 1, (kc + 1) & 1);
            asm volatile("cp.async.wait_group 1;" ::: "memory");
        } else {
            asm volatile("cp.async.wait_group 0;" ::: "memory");
        }
        __syncthreads();

        const uint32_t sa = smb + (kc & 1) * 2 * TILEB;
        const uint32_t sb = sa + TILEB;

        #pragma unroll
        for (int kk = 0; kk < 2; kk++) {           // two k16 steps in BK=32
            uint32_t af[2][4], bf[4][4];
            #pragma unroll
            for (int am = 0; am < 2; am++)
                ldsm4(af[am], sa + aRowOff + (uint32_t)am * 16 * ROWB + kk * 32);
            #pragma unroll
            for (int p = 0; p < 4; p++)
                ldsm4(bf[p], sb + bRowOff + (uint32_t)p * 16 * ROWB + kk * 32);

            #pragma unroll
            for (int am = 0; am < 2; am++)
                #pragma unroll
                for (int p = 0; p < 4; p++) {
                    asm volatile(
                        "mma.sync.aligned.m16n8k16.row.col.f32.f16.f16.f32 "
                        "{%0,%1,%2,%3}, {%4,%5,%6,%7}, {%8,%9}, {%0,%1,%2,%3};"
                        : "+f"(acc[am][2*p][0]), "+f"(acc[am][2*p][1]),
                          "+f"(acc[am][2*p][2]), "+f"(acc[am][2*p][3])
                        : "r"(af[am][0]), "r"(af[am][1]), "r"(af[am][2]), "r"(af[am][3]),
                          "r"(bf[p][0]), "r"(bf[p][1]));
                    asm volatile(
                        "mma.sync.aligned.m16n8k16.row.col.f32.f16.f16.f32 "
                        "{%0,%1,%2,%3}, {%4,%5,%6,%7}, {%8,%9}, {%0,%1,%2,%3};"
                        : "+f"(acc[am][2*p+1][0]), "+f"(acc[am][2*p+1][1]),
                          "+f"(acc[am][2*p+1][2]), "+f"(acc[am][2*p+1][3])
                        : "r"(af[am][0]), "r"(af[am][1]), "r"(af[am][2]), "r"(af[am][3]),
                          "r"(bf[p][2]), "r"(bf[p][3]));
                }
        }
        __syncthreads();
    }

    // ---------------- epilogue ----------------
    const int lrow = lid >> 2;
    const int lcol = (lid & 3) * 2;
    #pragma unroll
    for (int am = 0; am < 2; am++) {
        #pragma unroll
        for (int rr = 0; rr < 2; rr++) {
            const int grow = bm + wm * 32 + am * 16 + rr * 8 + lrow;
            const size_t rbase = (size_t)grow * Nd;
            #pragma unroll
            for (int an = 0; an < 8; an++) {
                const int gcol = bn + wn * 64 + an * 8 + lcol;
                float v0 = acc[am][an][rr * 2 + 0];
                float v1 = acc[am][an][rr * 2 + 1];
                if (mode & 1) {
                    const float2 bv = *(const float2*)&bias[gcol];
                    v0 += bv.x; v1 += bv.y;
                }
                if (mode & 2) { v0 = fmaxf(v0, 0.f); v1 = fmaxf(v1, 0.f); }
                if (mode & 8) {
                    const float2 rv = *(const float2*)&Res[rbase + gcol];
                    v0 += rv.x; v1 += rv.y;
                }
                if (mode & 4) {
                    const float2 cv = *(const float2*)&Cin[rbase + gcol];
                    v0 += cv.x; v1 += cv.y;
                }
                if (!(mode & 32))
                    *(float2*)&Cout[rbase + gcol] = make_float2(v0, v1);
                if (mode & 16)
                    *(__half2*)&Ohf[rbase + gcol] = __floats2half2_rn(v0, v1);
            }
        }
    }
}

// ---------------------------------------------------------------------------
// Kernel 4: feature-dim softmax attention (fp32 in, fp32 + fp16 out)
// ---------------------------------------------------------------------------
__global__ __launch_bounds__(128) void attn_k(
    const float* Qp, const float* __restrict__ Kp,
    const float* __restrict__ Vp, float* AO, __half* AOh)
{
    const int r = blockIdx.x;
    const int t = threadIdx.x;
    const size_t base = (size_t)r * A_;

    const float4 qp = ((const float4*)(Qp + base))[t];
    const float4 kp = ((const float4*)(Kp + base))[t];
    const float4 vp = ((const float4*)(Vp + base))[t];

    const float sc = 0.04419417382415922f;   // 1/sqrt(512)
    const float s0 = qp.x*kp.x*sc, s1 = qp.y*kp.y*sc;
    const float s2 = qp.z*kp.z*sc, s3 = qp.w*kp.w*sc;

    float mx = fmaxf(fmaxf(s0,s1), fmaxf(s2,s3));
    #pragma unroll
    for (int o = 16; o; o >>= 1) mx = fmaxf(mx, __shfl_xor_sync(0xffffffffu, mx, o));
    __shared__ float rmx[4];
    if ((t & 31) == 0) rmx[t >> 5] = mx;
    __syncthreads();
    mx = fmaxf(fmaxf(rmx[0], rmx[1]), fmaxf(rmx[2], rmx[3]));

    const float e0 = expf(s0-mx), e1 = expf(s1-mx);
    const float e2 = expf(s2-mx), e3 = expf(s3-mx);
    float smv = e0 + e1 + e2 + e3;
    #pragma unroll
    for (int o = 16; o; o >>= 1) smv += __shfl_xor_sync(0xffffffffu, smv, o);
    __shared__ float rsm[4];
    if ((t & 31) == 0) rsm[t >> 5] = smv;
    __syncthreads();
    smv = rsm[0] + rsm[1] + rsm[2] + rsm[3];

    const float inv = 1.f / smv;
    const float a0 = e0*inv*vp.x, a1 = e1*inv*vp.y;
    const float a2 = e2*inv*vp.z, a3 = e3*inv*vp.w;
    ((float4*)(AO + base))[t] = make_float4(a0, a1, a2, a3);
    __half2* oh = (__half2*)(AOh + base);
    oh[t*2+0] = __floats2half2_rn(a0, a1);
    oh[t*2+1] = __floats2half2_rn(a2, a3);
}

// ---------------------------------------------------------------------------
// Kernel 5: layernorm over M=2048, fp32 in -> fp16 out
// ---------------------------------------------------------------------------
__global__ __launch_bounds__(256) void ln_k(
    const float* __restrict__ X, __half* __restrict__ Y,
    const float* __restrict__ gln, const float* __restrict__ bln, int j)
{
    const int r  = blockIdx.x;
    const int t  = threadIdx.x;
    const int hh = r >> 14;                       // r / E_
    const size_t base = (size_t)r * M_;

    const float4* x4 = (const float4*)(X + base);
    const float4 x0 = x4[t];
    const float4 x1 = x4[t + 256];

    float s  = x0.x+x0.y+x0.z+x0.w + x1.x+x1.y+x1.z+x1.w;
    float sq = x0.x*x0.x+x0.y*x0.y+x0.z*x0.z+x0.w*x0.w
             + x1.x*x1.x+x1.y*x1.y+x1.z*x1.z+x1.w*x1.w;
    #pragma unroll
    for (int o = 16; o; o >>= 1) {
        s  += __shfl_xor_sync(0xffffffffu, s,  o);
        sq += __shfl_xor_sync(0xffffffffu, sq, o);
    }
    __shared__ float rs[8], rq[8];
    if ((t & 31) == 0) { rs[t>>5] = s; rq[t>>5] = sq; }
    __syncthreads();
    float st = 0.f, qt = 0.f;
    #pragma unroll
    for (int i = 0; i < 8; i++) { st += rs[i]; qt += rq[i]; }

    const float mu   = st * (1.f / M_);
    const float var  = fmaxf(qt * (1.f / M_) - mu*mu, 0.f);
    const float rstd = rsqrtf(var + 1e-5f);

    const size_t goff = (size_t)(hh * NRES_ + j) * M_;
    const float4* g4 = (const float4*)(gln + goff);
    const float4* b4 = (const float4*)(bln + goff);
    const float4 g0 = g4[t], g1 = g4[t+256];
    const float4 b0 = b4[t], b1 = b4[t+256];

    __half2* y2 = (__half2*)(Y + base);
    y2[t*2+0] = __floats2half2_rn((x0.x-mu)*rstd*g0.x + b0.x, (x0.y-mu)*rstd*g0.y + b0.y);
    y2[t*2+1] = __floats2half2_rn((x0.z-mu)*rstd*g0.z + b0.z, (x0.w-mu)*rstd*g0.w + b0.w);
    y2[(t+256)*2+0] = __floats2half2_rn((x1.x-mu)*rstd*g1.x + b1.x, (x1.y-mu)*rstd*g1.y + b1.y);
    y2[(t+256)*2+1] = __floats2half2_rn((x1.z-mu)*rstd*g1.z + b1.z, (x1.w-mu)*rstd*g1.w + b1.w);
}

// ---------------------------------------------------------------------------
// Orchestration
// ---------------------------------------------------------------------------
extern "C" void kernel_launch(void* const* d_in, const int* in_sizes, int n_in,
                              void* d_out, int out_size)
{
    const float* h    = (const float*)d_in[0];
    const float* rep  = (const float*)d_in[1];
    const int*   src  = (const int*)  d_in[2];
    const int*   dst  = (const int*)  d_in[3];
    const float* Wq   = (const float*)d_in[4];
    const float* bq   = (const float*)d_in[5];
    const float* Wk   = (const float*)d_in[6];
    const float* bk   = (const float*)d_in[7];
    const float* Wv   = (const float*)d_in[8];
    const float* bv   = (const float*)d_in[9];
    const float* W0   = (const float*)d_in[10];
    const float* b0   = (const float*)d_in[11];
    const float* Wr   = (const float*)d_in[12];
    const float* br   = (const float*)d_in[13];
    const float* gln  = (const float*)d_in[14];
    const float* bln  = (const float*)d_in[15];
    const float* Wms  = (const float*)d_in[16];
    const float* bms  = (const float*)d_in[17];
    const float* Wuas = (const float*)d_in[18];
    float* out = (float*)d_out;

    __half *Qh, *Kh, *AOh, *xnh, *mh, *HOh;
    __half *Wqt, *Wkt, *Wvt, *W0t, *Wrt, *Wmst, *Wuast;
    float *Qp, *Kp, *Vp, *mB;
    cudaGetSymbolAddress((void**)&Qh,   g_Qh);
    cudaGetSymbolAddress((void**)&Kh,   g_Kh);
    cudaGetSymbolAddress((void**)&Qp,   g_Qp);
    cudaGetSymbolAddress((void**)&Kp,   g_Kp);
    cudaGetSymbolAddress((void**)&Vp,   g_Vp);
    cudaGetSymbolAddress((void**)&AOh,  g_AOh);
    cudaGetSymbolAddress((void**)&mB,   g_m);
    cudaGetSymbolAddress((void**)&xnh,  g_xnh);
    cudaGetSymbolAddress((void**)&mh,   g_mh);
    cudaGetSymbolAddress((void**)&HOh,  g_HOh);
    cudaGetSymbolAddress((void**)&Wqt,  g_Wqt);
    cudaGetSymbolAddress((void**)&Wkt,  g_Wkt);
    cudaGetSymbolAddress((void**)&Wvt,  g_Wvt);
    cudaGetSymbolAddress((void**)&W0t,  g_W0t);
    cudaGetSymbolAddress((void**)&Wrt,  g_Wrt);
    cudaGetSymbolAddress((void**)&Wmst, g_Wmst);
    cudaGetSymbolAddress((void**)&Wuast,g_Wuast);

    auto tconv = [](const float* in, __half* o, int R, int C) {
        dim3 g(C / 32, R / 32);
        tconv_k<<<g, 256>>>(in, o, R, C);
    };
    auto gemm = [](const __half* Aa, const __half* Bt,
                   const float* bias, const float* Cin, const float* Res,
                   float* Co, __half* Oh, int Md, int Nd, int Kd, int mode) {
        dim3 grid(Nd / BNT, Md / BMT);
        tgemm_k<<<grid, 256>>>(Aa, Bt, bias, Cin, Res, Co, Oh, Nd, Kd, mode);
    };

    // 0. weight transpose + convert  (in [K,N] fp32 -> out [N,K] fp16)
    for (int hh = 0; hh < H_; hh++) {
        tconv(Wq + (size_t)hh*D_*A_, Wqt + (size_t)hh*A_*D_, D_, A_);
        tconv(Wk + (size_t)hh*D_*A_, Wkt + (size_t)hh*A_*D_, D_, A_);
        tconv(Wv + (size_t)hh*D_*A_, Wvt + (size_t)hh*A_*D_, D_, A_);
        tconv(W0 + (size_t)hh*A_*M_, W0t + (size_t)hh*M_*A_, A_, M_);
        for (int j = 0; j < NRES_; j++)
            tconv(Wr  + (size_t)(hh*NRES_+j)*M_*M_, Wrt + (size_t)(hh*NRES_+j)*M_*M_, M_, M_);
        tconv(Wms  + (size_t)hh*M_*A_, Wmst  + (size_t)hh*A_*M_, M_, A_);
        tconv(Wuas + (size_t)hh*A_*D_, Wuast + (size_t)hh*D_*A_, A_, D_);
    }

    // 1. gather + normalize + seed out = Q - K  (+ fp16 Q,K)
    gather_k<<<E_, 256>>>(h, rep, src, dst, out);

    // 2. per-head QKV projections
    for (int hh = 0; hh < H_; hh++) {
        const size_t wOff = (size_t)hh * A_ * D_;
        const size_t oOff = (size_t)hh * E_ * A_;
        gemm(Qh, Wqt + wOff, bq + hh*A_, nullptr, nullptr, Qp + oOff, nullptr, E_, A_, D_, 1);
        gemm(Kh, Wkt + wOff, bk + hh*A_, nullptr, nullptr, Kp + oOff, nullptr, E_, A_, D_, 1);
        gemm(Kh, Wvt + wOff, bv + hh*A_, nullptr, nullptr, Vp + oOff, nullptr, E_, A_, D_, 1);
    }

    // 3. feature-dim softmax attention; attn_out -> Qp (fp32) + AOh (fp16)
    attn_k<<<H_ * E_, 128>>>(Qp, Kp, Vp, Qp, AOh);

    // 4. m = attn_out @ W0 + b0
    for (int hh = 0; hh < H_; hh++)
        gemm(AOh + (size_t)hh*E_*A_, W0t + (size_t)hh*M_*A_, b0 + hh*M_,
             nullptr, nullptr, mB + (size_t)hh*E_*M_, nullptr, E_, M_, A_, 1);

    // 5. ResNet blocks: xn = LN(m); m += relu(xn @ Wr + br)
    for (int j = 0; j < NRES_; j++) {
        ln_k<<<H_ * E_, 256>>>(mB, xnh, gln, bln, j);
        const int mode = (j == NRES_ - 1) ? (1|2|4|16) : (1|2|4);
        for (int hh = 0; hh < H_; hh++) {
            const size_t mOff = (size_t)hh * E_ * M_;
            const size_t wOff = (size_t)(hh * NRES_ + j) * M_ * M_;
            gemm(xnh + mOff, Wrt + wOff, br + (hh*NRES_ + j)*M_,
                 mB + mOff, nullptr, mB + mOff, mh + mOff, E_, M_, M_, mode);
        }
    }

    // 6. head_out = m @ Wms + bms + attn_out  (fp16 only)
    for (int hh = 0; hh < H_; hh++)
        gemm(mh + (size_t)hh*E_*M_, Wmst + (size_t)hh*A_*M_, bms + hh*A_,
             nullptr, Qp + (size_t)hh*E_*A_, nullptr, HOh + (size_t)hh*E_*A_,
             E_, A_, M_, 1|8|16|32);

    // 7. out += head_out[h] @ Wuas[h]   (out already holds Q-K)
    for (int hh = 0; hh < H_; hh++)
        gemm(HOh + (size_t)hh*E_*A_, Wuast + (size_t)hh*D_*A_, nullptr,
             out, nullptr, out, nullptr, E_, D_, A_, 4);
}